// round 5
// baseline (speedup 1.0000x reference)
#include <cuda_runtime.h>
#include <cuda_fp16.h>
#include <math.h>
#include <stdint.h>

// ---------------------------------------------------------------------------
// GTN: H = diag(s) * (HA_dense_fp16 @ M_fp16) per channel, via mma.sync
// (base-sm_100-safe: no tcgen05/TMA — ldmatrix + mma.sync.m16n8k16 + cp.async)
// Output: y[512*8] | all_Ws[3*2*5] | H[2*2048*2048]
// ---------------------------------------------------------------------------

#define NN    2048
#define NE    5
#define NC    2
#define CAP   256
#define NT    512
#define XD    512
#define WOUT  128
#define NCLS  8

#define Y_OFF  0
#define WS_OFF (NT * NCLS)
#define H_OFF  (WS_OFF + 3 * NC * NE)   // 4126 floats (8B aligned)

// GEMM tiling
#define MT_   256
#define NT_   128
#define KS_   32
#define NKC   (NN / KS_)                // 64 stages
#define A_STRIDE 80                     // 64B row + 16B pad (conflict-free ldmatrix)
#define B_STRIDE 272                    // 256B row + 16B pad
#define A_STAGE  (MT_ * A_STRIDE)       // 20480
#define B_STAGE  (KS_ * B_STRIDE)       // 8704
#define GEMM_SMEM (2 * A_STAGE + 2 * B_STAGE)  // 58368

// ------------------------- static device scratch ---------------------------
__device__ int    g_cnt[NN];
__device__ int    g_cols[NN * CAP];
__device__ float  g_hav [NC][NN * CAP];
__device__ float  g_hbv [NC][NN * CAP];
__device__ float  g_hb2v[NC][NN * CAP];
__device__ float  g_s[3][NC][NE];
__device__ float  g_rB  [NC][NN];
__device__ float  g_rB2 [NC][NN];
__device__ float  g_rM  [NC][NN];
__device__ float  g_deg0[NC][NN];
__device__ float  g_scale[NC][NN];
__device__ __align__(16) __half g_Mh[NC][NN][NN];   // M = HB@HB2, fp16
__device__ __align__(16) __half g_Ad[NC][NN][NN];   // dense fp16 HA
__device__ float  g_gwT[XD][WOUT];

// ------------------------------ helpers ------------------------------------
__device__ __forceinline__ uint32_t smem_u32(const void* p) {
    uint32_t a;
    asm("{ .reg .u64 t; cvta.to.shared.u64 t, %1; cvt.u32.u64 %0, t; }" : "=r"(a) : "l"(p));
    return a;
}
__device__ __forceinline__ float warpSum(float v) {
    #pragma unroll
    for (int o = 16; o > 0; o >>= 1) v += __shfl_down_sync(0xffffffffu, v, o);
    return v;
}
__device__ __forceinline__ void cp_async16(uint32_t dst, const void* src) {
    asm volatile("cp.async.cg.shared.global [%0], [%1], 16;" :: "r"(dst), "l"(src) : "memory");
}
__device__ __forceinline__ void ldsm_x4(uint32_t* r, uint32_t addr) {
    asm volatile("ldmatrix.sync.aligned.m8n8.x4.shared.b16 {%0,%1,%2,%3}, [%4];"
        : "=r"(r[0]), "=r"(r[1]), "=r"(r[2]), "=r"(r[3]) : "r"(addr));
}
__device__ __forceinline__ void ldsm_x2t(uint32_t* r, uint32_t addr) {
    asm volatile("ldmatrix.sync.aligned.m8n8.x2.trans.shared.b16 {%0,%1}, [%2];"
        : "=r"(r[0]), "=r"(r[1]) : "r"(addr));
}
__device__ __forceinline__ void mma16816(float* d, const uint32_t* a, const uint32_t* b) {
    asm volatile(
        "mma.sync.aligned.m16n8k16.row.col.f32.f16.f16.f32 "
        "{%0,%1,%2,%3}, {%4,%5,%6,%7}, {%8,%9}, {%0,%1,%2,%3};"
        : "+f"(d[0]), "+f"(d[1]), "+f"(d[2]), "+f"(d[3])
        : "r"(a[0]), "r"(a[1]), "r"(a[2]), "r"(a[3]), "r"(b[0]), "r"(b[1]));
}

// --------------------------- kernel 1: init --------------------------------
__global__ void k_init(const float* __restrict__ w1, const float* __restrict__ w2,
                       const float* __restrict__ w3, float* __restrict__ out_ws) {
    int tid = threadIdx.x;
    for (int i = tid; i < NN; i += blockDim.x) g_cnt[i] = 0;
    if (tid < 3 * NC) {
        int m = tid / NC, c = tid % NC;
        const float* w = (m == 0 ? w1 : (m == 1 ? w2 : w3)) + c * NE;
        float mx = w[0];
        #pragma unroll
        for (int e = 1; e < NE; e++) mx = fmaxf(mx, w[e]);
        float ex[NE], s = 0.f;
        #pragma unroll
        for (int e = 0; e < NE; e++) { ex[e] = expf(w[e] - mx); s += ex[e]; }
        float inv = 1.f / s;
        #pragma unroll
        for (int e = 0; e < NE; e++) {
            float v = ex[e] * inv;
            g_s[m][c][e] = v;
            out_ws[m * NC * NE + c * NE + e] = v;
        }
    }
}

// ------------------- kernel 2: build sparse pattern + values ---------------
__global__ void k_fill(const float* __restrict__ A) {
    int i = blockIdx.x;
    float s1[NC][NE], s2[NC][NE], s3[NC][NE];
    #pragma unroll
    for (int c = 0; c < NC; c++)
        #pragma unroll
        for (int e = 0; e < NE; e++) {
            s1[c][e] = g_s[0][c][e]; s2[c][e] = g_s[1][c][e]; s3[c][e] = g_s[2][c][e];
        }
    for (int j = threadIdx.x; j < NN; j += blockDim.x) {
        float a[NE];
        bool nz = false;
        #pragma unroll
        for (int e = 0; e < NE; e++) {
            a[e] = A[(size_t)e * NN * NN + (size_t)i * NN + j];
            nz |= (a[e] != 0.f);
        }
        if (nz) {
            int slot = atomicAdd(&g_cnt[i], 1);
            if (slot < CAP) {
                int p = i * CAP + slot;
                g_cols[p] = j;
                #pragma unroll
                for (int c = 0; c < NC; c++) {
                    float va = 0.f, vb = 0.f, vb2 = 0.f;
                    #pragma unroll
                    for (int e = 0; e < NE; e++) {
                        va  += s1[c][e] * a[e];
                        vb  += s2[c][e] * a[e];
                        vb2 += s3[c][e] * a[e];
                    }
                    g_hav[c][p] = va; g_hbv[c][p] = vb; g_hb2v[c][p] = vb2;
                }
            }
        }
    }
}

// --------------- kernel 3: row sums of HB, HB2 -----------------------------
__global__ void k_rowstats() {
    int r = blockIdx.x;
    int cnt = min(g_cnt[r], CAP);
    float a0 = 0, a1 = 0, b0 = 0, b1 = 0;
    for (int t = threadIdx.x; t < cnt; t += blockDim.x) {
        int p = r * CAP + t;
        a0 += g_hbv[0][p];  a1 += g_hbv[1][p];
        b0 += g_hb2v[0][p]; b1 += g_hb2v[1][p];
    }
    a0 = warpSum(a0); a1 = warpSum(a1); b0 = warpSum(b0); b1 = warpSum(b1);
    __shared__ float sh[4][4];
    int w = threadIdx.x >> 5, lane = threadIdx.x & 31;
    if (lane == 0) { sh[w][0] = a0; sh[w][1] = a1; sh[w][2] = b0; sh[w][3] = b1; }
    __syncthreads();
    if (threadIdx.x == 0) {
        float v0 = 0, v1 = 0, v2 = 0, v3 = 0;
        for (int k = 0; k < 4; k++) { v0 += sh[k][0]; v1 += sh[k][1]; v2 += sh[k][2]; v3 += sh[k][3]; }
        g_rB[0][r] = v0; g_rB[1][r] = v1; g_rB2[0][r] = v2; g_rB2[1][r] = v3;
    }
}

// ---- kernel 4: deg0 + rowsum(M) -------------------------------------------
__global__ void k_deg() {
    int r = blockIdx.x;
    int cnt = min(g_cnt[r], CAP);
    float d0 = 0, d1 = 0, m0 = 0, m1 = 0;
    for (int t = threadIdx.x; t < cnt; t += blockDim.x) {
        int p = r * CAP + t;
        int col = g_cols[p];
        d0 += g_hav[0][p] * g_rB[0][col];
        d1 += g_hav[1][p] * g_rB[1][col];
        m0 += g_hbv[0][p] * g_rB2[0][col];
        m1 += g_hbv[1][p] * g_rB2[1][col];
    }
    d0 = warpSum(d0); d1 = warpSum(d1); m0 = warpSum(m0); m1 = warpSum(m1);
    __shared__ float sh[4][4];
    int w = threadIdx.x >> 5, lane = threadIdx.x & 31;
    if (lane == 0) { sh[w][0] = d0; sh[w][1] = d1; sh[w][2] = m0; sh[w][3] = m1; }
    __syncthreads();
    if (threadIdx.x == 0) {
        float v0 = 0, v1 = 0, v2 = 0, v3 = 0;
        for (int k = 0; k < 4; k++) { v0 += sh[k][0]; v1 += sh[k][1]; v2 += sh[k][2]; v3 += sh[k][3]; }
        g_deg0[0][r] = v0; g_deg0[1][r] = v1; g_rM[0][r] = v2; g_rM[1][r] = v3;
    }
}

// ---- kernel 5: final per-row scale ----------------------------------------
__global__ void k_scalek() {
    int r = blockIdx.x;
    int cnt = min(g_cnt[r], CAP);
    float t0 = 0, t1 = 0;
    for (int t = threadIdx.x; t < cnt; t += blockDim.x) {
        int p = r * CAP + t;
        int col = g_cols[p];
        t0 += g_hav[0][p] * g_rM[0][col];
        t1 += g_hav[1][p] * g_rM[1][col];
    }
    t0 = warpSum(t0); t1 = warpSum(t1);
    __shared__ float sh[4][2];
    int w = threadIdx.x >> 5, lane = threadIdx.x & 31;
    if (lane == 0) { sh[w][0] = t0; sh[w][1] = t1; }
    __syncthreads();
    if (threadIdx.x == 0) {
        float tt[2] = {0.f, 0.f};
        for (int k = 0; k < 4; k++) { tt[0] += sh[k][0]; tt[1] += sh[k][1]; }
        #pragma unroll
        for (int c = 0; c < NC; c++) {
            float dg0 = g_deg0[c][r];
            float d0 = (dg0 > 0.f) ? (1.f / sqrtf(dg0)) : 0.f;
            float dg1 = d0 * tt[c];
            float d1 = (dg1 > 0.f) ? (1.f / sqrtf(dg1)) : 0.f;
            g_scale[c][r] = d0 * d1;
        }
    }
}

// ---------- kernel 6: M = HB @ HB2 (sparse x sparse -> dense fp16) ---------
__global__ void k_M() {
    int k = blockIdx.x, c = blockIdx.y;
    __shared__ float acc[NN];
    for (int j = threadIdx.x; j < NN; j += blockDim.x) acc[j] = 0.f;
    __syncthreads();
    int cnt = min(g_cnt[k], CAP);
    int warp = threadIdx.x >> 5, lane = threadIdx.x & 31;
    for (int pi = warp; pi < cnt; pi += 8) {
        int p = k * CAP + pi;
        int l = g_cols[p];
        float hb = g_hbv[c][p];
        int cl = min(g_cnt[l], CAP);
        for (int qi = lane; qi < cl; qi += 32) {
            int q = l * CAP + qi;
            atomicAdd(&acc[g_cols[q]], hb * g_hb2v[c][q]);
        }
    }
    __syncthreads();
    __half2* mrow = reinterpret_cast<__half2*>(&g_Mh[c][k][0]);
    for (int j2 = threadIdx.x; j2 < NN / 2; j2 += blockDim.x)
        mrow[j2] = __floats2half2_rn(acc[2 * j2], acc[2 * j2 + 1]);
}

// ---------- kernel 6b: densify HA into fp16 --------------------------------
__global__ void k_densify() {
    int i = blockIdx.x, c = blockIdx.y;
    uint4* row = reinterpret_cast<uint4*>(&g_Ad[c][i][0]);
    for (int t = threadIdx.x; t < 256; t += blockDim.x)
        row[t] = make_uint4(0u, 0u, 0u, 0u);
    __syncthreads();
    int cnt = min(g_cnt[i], CAP);
    for (int t = threadIdx.x; t < cnt; t += blockDim.x) {
        int p = i * CAP + t;
        g_Ad[c][i][g_cols[p]] = __float2half(g_hav[c][p]);
    }
}

// ---------- kernel 7: dense fp16 GEMM via mma.sync -------------------------
// CTA tile 256x128, K staged 32 wide, double-buffered cp.async.
// 16 warps in 4(m) x 4(n); warp tile 64x32; fragments via ldmatrix.
__global__ void __launch_bounds__(512, 1) k_gemm(float* __restrict__ H) {
    extern __shared__ char dsm[];
    const uint32_t sb = smem_u32(dsm);
    const int c  = blockIdx.z;
    const int i0 = blockIdx.y * MT_;
    const int j0 = blockIdx.x * NT_;
    const int tid = threadIdx.x, lane = tid & 31, wid = tid >> 5;
    const int wm = wid >> 2, wn = wid & 3;

    const uint32_t Abuf[2] = { sb, sb + A_STAGE };
    const uint32_t Bbuf[2] = { sb + 2 * A_STAGE, sb + 2 * A_STAGE + B_STAGE };

    float acc[4][4][4];
    #pragma unroll
    for (int a = 0; a < 4; a++)
        #pragma unroll
        for (int b = 0; b < 4; b++)
            #pragma unroll
            for (int d = 0; d < 4; d++) acc[a][b][d] = 0.f;

    auto load_stage = [&](int buf, int kc) {
        const int k0 = kc * KS_;
        #pragma unroll
        for (int t = 0; t < 2; t++) {                       // A: 1024 16B chunks
            int idx = tid + t * 512;
            int r = idx >> 2, p = idx & 3;
            cp_async16(Abuf[buf] + r * A_STRIDE + p * 16, &g_Ad[c][i0 + r][k0 + p * 8]);
        }
        {                                                   // B: 512 16B chunks
            int kr = tid >> 4, p = tid & 15;
            cp_async16(Bbuf[buf] + kr * B_STRIDE + p * 16, &g_Mh[c][k0 + kr][j0 + p * 8]);
        }
        asm volatile("cp.async.commit_group;" ::: "memory");
    };

    load_stage(0, 0);
    for (int kc = 0; kc < NKC; kc++) {
        const int s = kc & 1;
        if (kc + 1 < NKC) {
            load_stage(s ^ 1, kc + 1);
            asm volatile("cp.async.wait_group 1;" ::: "memory");
        } else {
            asm volatile("cp.async.wait_group 0;" ::: "memory");
        }
        __syncthreads();
        #pragma unroll
        for (int ks = 0; ks < 2; ks++) {
            uint32_t afr[4][4], bfr[4][2];
            #pragma unroll
            for (int mt = 0; mt < 4; mt++) {
                uint32_t addr = Abuf[s] + (uint32_t)(wm * 64 + mt * 16 + (lane & 15)) * A_STRIDE
                              + ks * 32 + (lane >> 4) * 16;
                ldsm_x4(afr[mt], addr);
            }
            #pragma unroll
            for (int nt = 0; nt < 4; nt++) {
                uint32_t addr = Bbuf[s] + (uint32_t)(ks * 16 + (lane & 15)) * B_STRIDE
                              + (uint32_t)(wn * 32 + nt * 8) * 2;
                ldsm_x2t(bfr[nt], addr);
            }
            #pragma unroll
            for (int mt = 0; mt < 4; mt++)
                #pragma unroll
                for (int nt = 0; nt < 4; nt++)
                    mma16816(acc[mt][nt], afr[mt], bfr[nt]);
        }
        __syncthreads();
    }

    // epilogue: scale rows, store float2 per fragment pair
    #pragma unroll
    for (int mt = 0; mt < 4; mt++) {
        #pragma unroll
        for (int h = 0; h < 2; h++) {
            int row = i0 + wm * 64 + mt * 16 + (lane >> 2) + h * 8;
            float sc = g_scale[c][row];
            float* hrow = &H[(size_t)c * NN * NN + (size_t)row * NN];
            #pragma unroll
            for (int nt = 0; nt < 4; nt++) {
                int col = j0 + wn * 32 + nt * 8 + (lane & 3) * 2;
                float2 v = make_float2(sc * acc[mt][nt][2 * h], sc * acc[mt][nt][2 * h + 1]);
                *reinterpret_cast<float2*>(&hrow[col]) = v;
            }
        }
    }
}

// -------------------- kernel 8: transpose gcn_w ----------------------------
__global__ void k_transpose(const float* __restrict__ gw) {
    int idx = blockIdx.x * blockDim.x + threadIdx.x;
    if (idx < WOUT * XD) {
        int jj = idx / XD, kk = idx % XD;
        g_gwT[kk][jj] = gw[idx];
    }
}

// -------------------- kernel 9: classification head ------------------------
__global__ void k_head(const float* __restrict__ Xm, const float* __restrict__ gcn_b,
                       const float* __restrict__ lin_w, const float* __restrict__ lin_b,
                       const int* __restrict__ tx, float* __restrict__ y) {
    int t = blockIdx.x;
    int row = tx[t];
    __shared__ float xr[XD];
    __shared__ float h[WOUT];
    for (int k = threadIdx.x; k < XD; k += blockDim.x)
        xr[k] = Xm[(size_t)row * XD + k];
    __syncthreads();
    int j = threadIdx.x;
    float acc = gcn_b[j];
    #pragma unroll 8
    for (int k = 0; k < XD; k++) acc += g_gwT[k][j] * xr[k];
    h[j] = fmaxf(acc, 0.f);
    __syncthreads();
    if (j < NCLS) {
        float acc2 = lin_b[j];
        #pragma unroll 4
        for (int m = 0; m < WOUT; m++)
            acc2 += (lin_w[j * (NC * WOUT) + m] + lin_w[j * (NC * WOUT) + WOUT + m]) * h[m];
        y[t * NCLS + j] = acc2;
    }
}

// ------------------------------ launch -------------------------------------
extern "C" void kernel_launch(void* const* d_in, const int* in_sizes, int n_in,
                              void* d_out, int out_size) {
    const float* A     = (const float*)d_in[0];
    const float* X     = (const float*)d_in[1];
    const float* w01   = (const float*)d_in[2];
    const float* w02   = (const float*)d_in[3];
    const float* w11   = (const float*)d_in[4];
    const float* gcn_w = (const float*)d_in[5];
    const float* gcn_b = (const float*)d_in[6];
    const float* lin_w = (const float*)d_in[7];
    const float* lin_b = (const float*)d_in[8];
    const int*   tx    = (const int*)d_in[9];
    float* out = (float*)d_out;

    cudaFuncSetAttribute(k_gemm, cudaFuncAttributeMaxDynamicSharedMemorySize, GEMM_SMEM);

    k_init<<<1, 256>>>(w01, w02, w11, out + WS_OFF);
    k_fill<<<NN, 256>>>(A);
    k_rowstats<<<NN, 128>>>();
    k_deg<<<NN, 128>>>();
    k_scalek<<<NN, 128>>>();
    k_M<<<dim3(NN, NC), 256>>>();
    k_densify<<<dim3(NN, NC), 256>>>();
    k_gemm<<<dim3(NN / NT_, NN / MT_, NC), 512, GEMM_SMEM>>>(out + H_OFF);
    k_transpose<<<(WOUT * XD + 255) / 256, 256>>>(gcn_w);
    k_head<<<NT, 128>>>(X, gcn_b, lin_w, lin_b, tx, out + Y_OFF);
}